// round 4
// baseline (speedup 1.0000x reference)
#include <cuda_runtime.h>

#define B_   32
#define Q_   256
#define M_   128
#define P_   64
#define C1_  21
#define NBLK (B_ * M_)   // 4096 blocks, one per (b, m)

// Per-block partials: [0:NBLK) = ce sums, [NBLK:2N) = poly, [2N:3N) = dir.
// Written entirely by kernel 1 every call before kernel 2 reads -> no init needed.
__device__ float g_part[3 * NBLK];

__global__ __launch_bounds__(64) void crit_main(
    const float* __restrict__ logits,       // [B, Q, 21]
    const float* __restrict__ pred_poly,    // [B, Q, P, 2]
    const float* __restrict__ tgt_poly,     // [B, M, P, 2]
    const int*   __restrict__ src_idx,      // [B, M]
    const int*   __restrict__ labels)       // [B, M]
{
    __shared__ float2 s_src[P_];
    __shared__ float2 s_tgt[P_];
    __shared__ float  s_red[2];
    __shared__ float  s_ce[2];

    const int blk  = blockIdx.x;
    const int b    = blk >> 7;       // / M_
    const int m    = blk & (M_ - 1);
    const int tid  = threadIdx.x;    // 0..63
    const int w    = tid >> 5;
    const int lane = tid & 31;

    const int q_m = src_idx[b * M_ + m];

    // Cooperative load of both polylines into smem (one float2 per thread).
    const float2* tp = reinterpret_cast<const float2*>(tgt_poly)  + (size_t)(b * M_ + m)   * P_;
    const float2* sp = reinterpret_cast<const float2*>(pred_poly) + (size_t)(b * Q_ + q_m) * P_;
    const float2 myt = tp[tid];
    const float2 mys = sp[tid];
    s_tgt[tid] = myt;
    s_src[tid] = mys;
    __syncthreads();

    // ---- chamfer: thread i owns src point i (rowmin) and tgt point i (colmin) ----
    float rowmin = 3.4e38f;
    float colmin = 3.4e38f;
#pragma unroll
    for (int j = 0; j < P_; ++j) {
        const float2 tj = s_tgt[j];   // broadcast (conflict-free)
        const float2 sj = s_src[j];   // broadcast
        const float d1 = fabsf(mys.x - tj.x) + fabsf(mys.y - tj.y); // d(i, j) -> row i
        const float d2 = fabsf(sj.x - myt.x) + fabsf(sj.y - myt.y); // d(j, i) -> col i
        rowmin = fminf(rowmin, d1);
        colmin = fminf(colmin, d2);
    }
    float v = rowmin + colmin;
#pragma unroll
    for (int o = 16; o > 0; o >>= 1) v += __shfl_xor_sync(0xffffffffu, v, o);
    if (lane == 0) s_red[w] = v;

    // ---- classification loss for query q = 2m + w (warp w handles one query) ----
    // Emulate scatter .at[].set with duplicate indices: LAST write wins (max m).
    const int q = 2 * m + w;
    const int* si = src_idx + b * M_;
    int best = -1;
#pragma unroll
    for (int k = 0; k < 4; ++k) {
        const int mm = lane + k * 32;          // increases with k -> later k wins within lane
        if (si[mm] == q) best = mm;
    }
    best = __reduce_max_sync(0xffffffffu, best);
    const int tc = (best >= 0) ? labels[b * M_ + best] : (C1_ - 1);

    const float logit = (lane < C1_) ? logits[((size_t)(b * Q_ + q)) * C1_ + lane] : -3.4e38f;
    float mx = logit;
#pragma unroll
    for (int o = 16; o > 0; o >>= 1) mx = fmaxf(mx, __shfl_xor_sync(0xffffffffu, mx, o));
    float e = (lane < C1_) ? __expf(logit - mx) : 0.0f;
#pragma unroll
    for (int o = 16; o > 0; o >>= 1) e += __shfl_xor_sync(0xffffffffu, e, o);
    const float ltc = __shfl_sync(0xffffffffu, logit, tc);
    const float ce  = __logf(e) + mx - ltc;    // logsumexp - x[tc]
    if (lane == 0) s_ce[w] = ce;

    __syncthreads();
    if (tid == 0) {
        const float poly = (s_red[0] + s_red[1]) * (0.5f / (float)P_);

        // ---- direction loss ----
        const float2 s0 = s_src[0], s1 = s_src[P_ - 1];
        const float2 t0 = s_tgt[0], t1 = s_tgt[P_ - 1];
        const float sdx = s1.x - s0.x, sdy = s1.y - s0.y;
        const float tdx = t1.x - t0.x, tdy = t1.y - t0.y;
        const float sn = sqrtf(sdx * sdx + sdy * sdy) + 1e-6f;
        const float tn = sqrtf(tdx * tdx + tdy * tdy) + 1e-6f;
        const float cosv = (sdx * tdx + sdy * tdy) / (sn * tn);

        g_part[blk]             = s_ce[0] + s_ce[1];
        g_part[NBLK + blk]      = poly;
        g_part[2 * NBLK + blk]  = 1.0f - cosv;
    }
}

__global__ __launch_bounds__(256) void crit_reduce(float* __restrict__ out)
{
    __shared__ double sm[24];
    const int tid  = threadIdx.x;
    const int w    = tid >> 5;
    const int lane = tid & 31;

    double a = 0.0, bb = 0.0, c = 0.0;
    for (int k = tid; k < NBLK; k += 256) {
        a  += (double)g_part[k];
        bb += (double)g_part[NBLK + k];
        c  += (double)g_part[2 * NBLK + k];
    }
#pragma unroll
    for (int o = 16; o > 0; o >>= 1) {
        a  += __shfl_xor_sync(0xffffffffu, a,  o);
        bb += __shfl_xor_sync(0xffffffffu, bb, o);
        c  += __shfl_xor_sync(0xffffffffu, c,  o);
    }
    if (lane == 0) { sm[w] = a; sm[8 + w] = bb; sm[16 + w] = c; }
    __syncthreads();
    if (tid == 0) {
        double A = 0.0, Bv = 0.0, Cv = 0.0;
#pragma unroll
        for (int i = 0; i < 8; ++i) { A += sm[i]; Bv += sm[8 + i]; Cv += sm[16 + i]; }
        out[0] = (float)(A  / (double)(B_ * Q_));   // mean over B*Q
        out[1] = (float)(Bv / (double)(B_ * M_));   // / num_polylines
        out[2] = (float)(Cv / (double)(B_ * M_));
    }
}

extern "C" void kernel_launch(void* const* d_in, const int* in_sizes, int n_in,
                              void* d_out, int out_size)
{
    const float* logits    = (const float*)d_in[0];
    const float* pred_poly = (const float*)d_in[1];
    const float* tgt_poly  = (const float*)d_in[2];
    const int*   src_idx   = (const int*)d_in[3];
    const int*   labels    = (const int*)d_in[4];

    crit_main<<<NBLK, 64>>>(logits, pred_poly, tgt_poly, src_idx, labels);
    crit_reduce<<<1, 256>>>((float*)d_out);
}